// round 8
// baseline (speedup 1.0000x reference)
#include <cuda_runtime.h>

// LQR via Riccati recursion. T=128, n_state=16, n_ctrl=8, n_all=24.
// Single CTA, 160 threads. Warp-specialized B+CD:
//   Phase A: W = P*F (96 thr) + K->global copy (tid 96..135)         -> bar
//   Phase B/CD: warp0: Quu+qu then Cholesky (syncwarp only);
//               warp1: Qux, named bar.sync(1,64) with warp0;
//               warps2-4: Qxx + qx (inside CD shadow)                -> bar
//   Phase E: P, p, Acl, bias                                         -> bar

constexpr int TT = 128, NS = 16, NC = 8, NA = 24;
constexpr int NTHR = 160;
constexpr int CST4 = NA * NA / 4;  // 144 float4 per stage of C

constexpr int QS = 28;  // sQ row stride (floats)
constexpr int WS = 28;  // sW row stride
constexpr int PS = 20;  // sP row stride
constexpr int AS = 17;  // Acl row stride

__device__ __align__(16) float g_K[TT][NC][NS];
__device__ float g_kk[TT][NC];
__device__ __align__(16) float g_P[TT][NS][NS];
__device__ float g_p[TT][NS];

__global__ void __launch_bounds__(NTHR, 1) lqr_kernel(
    const float* __restrict__ A, const float* __restrict__ B,
    const float* __restrict__ x0, const float* __restrict__ C,
    const float* __restrict__ c, float* __restrict__ out)
{
    extern __shared__ float sAcl[];            // [TT][NS][AS]
    __shared__ __align__(16) float sF[NS][NA]; // [A B]
    __shared__ __align__(16) float sW[NS][WS];
    __shared__ __align__(16) float sQ[NA][QS];
    __shared__ __align__(16) float sP[NS][PS];
    __shared__ __align__(16) float sK[NC][NS];
    __shared__ float sq[NA], sp[NS], skk[NC];
    __shared__ float sBias[TT][NS];
    __shared__ float sX[TT][NS];

    const int tid = threadIdx.x;

    for (int idx = tid; idx < NS * NA; idx += NTHR) {
        int i = idx / NA, j = idx % NA;
        sF[i][j] = (j < NS) ? A[i * NS + j] : B[i * NC + (j - NS)];
    }
    __syncthreads();

    // ---- B-phase role setup ----
    // tid 0..15 : Quu quad  (row NS+(tid&7), quad 4+(tid>>3))
    // tid 16..23: qu scalar (row NS+(tid-16))
    // tid 24..31: none
    // tid 32..63: Qux quad  (row NS+((tid-32)&7), quad (tid-32)>>3)
    // tid 64..159: Qxx quad (task=tid-64: row task/6, quad task%6)
    //   tid 64..79 additionally: qx scalar (i = tid-64)
    int rrow = 0, rq = 0;
    bool quad_task = false;
    if (tid < 16)               { rrow = NS + (tid & 7);        rq = 4 + (tid >> 3); quad_task = true; }
    else if (tid < 24)          { rrow = NS + (tid - 16); }
    else if (tid >= 32 && tid < 64) { int l = tid - 32; rrow = NS + (l & 7); rq = l >> 3; quad_task = true; }
    else if (tid >= 64)         { int task = tid - 64;  rrow = task / 6;     rq = task % 6; quad_task = true; }

    float Fc[NS];
    if (tid < 24 || tid >= 32) {
#pragma unroll
        for (int k = 0; k < NS; ++k) Fc[k] = sF[k][rrow];
    }

    const float4* C4 = (const float4*)C;
    float4 creg = make_float4(0.f, 0.f, 0.f, 0.f);
    float  cq   = 0.f;
    if (quad_task) creg = C4[(TT - 1) * CST4 + rrow * 6 + rq];
    if (tid >= 16 && tid < 24) cq = c[(TT - 1) * NA + rrow];
    if (tid >= 64 && tid < 80) cq = c[(TT - 1) * NA + (tid - 64)];

    // ---------------- Backward Riccati pass ----------------
#pragma unroll 1
    for (int t = TT - 1; t >= 0; --t) {
        const bool notlast = (t != TT - 1);

        if (notlast) {
            // ---- Phase A: W = P * F (96 thr) + K_{t+1} -> global copy ----
            if (tid < 96) {
                int i = tid & 15, jq = tid >> 4;
                float4 s = make_float4(0.f, 0.f, 0.f, 0.f);
#pragma unroll
                for (int kq = 0; kq < 4; ++kq) {
                    float4 p4 = *(const float4*)&sP[i][4 * kq];
#pragma unroll
                    for (int kk2 = 0; kk2 < 4; ++kk2) {
                        float p = (kk2 == 0) ? p4.x : (kk2 == 1) ? p4.y : (kk2 == 2) ? p4.z : p4.w;
                        float4 f = *(const float4*)&sF[4 * kq + kk2][4 * jq];
                        s.x = fmaf(p, f.x, s.x); s.y = fmaf(p, f.y, s.y);
                        s.z = fmaf(p, f.z, s.z); s.w = fmaf(p, f.w, s.w);
                    }
                }
                *(float4*)&sW[i][4 * jq] = s;
            } else if (tid < 128) {
                ((float4*)&g_K[t + 1][0][0])[tid - 96] = ((const float4*)&sK[0][0])[tid - 96];
            } else if (tid < 136) {
                g_kk[t + 1][tid - 128] = skk[tid - 128];
            }
            __syncthreads();
        }

        // ---- Phase B + CD ----
        if (tid < 64) {
            if (tid < 32) {
                // warp 0: Quu quads + qu, then straight into Cholesky
                if (tid < 16) {
                    float4 s = creg;
                    if (notlast) {
#pragma unroll
                        for (int k = 0; k < NS; ++k) {
                            float f = Fc[k];
                            float4 w = *(const float4*)&sW[k][4 * rq];
                            s.x = fmaf(f, w.x, s.x); s.y = fmaf(f, w.y, s.y);
                            s.z = fmaf(f, w.z, s.z); s.w = fmaf(f, w.w, s.w);
                        }
                    }
                    *(float4*)&sQ[rrow][4 * rq] = s;
                    if (t > 0) creg = C4[(t - 1) * CST4 + rrow * 6 + rq];
                } else if (tid < 24) {
                    float s = cq;
                    if (notlast) {
#pragma unroll
                        for (int k = 0; k < NS; ++k) s = fmaf(Fc[k], sp[k], s);
                    }
                    sq[rrow] = s;
                    if (t > 0) cq = c[(t - 1) * NA + rrow];
                }
                __syncwarp();

                float Lm[NC][NC], invd[NC];
                if (tid <= NS) {
                    // factorize Quu (right-looking, scaled columns, rsqrtf)
#pragma unroll
                    for (int j = 0; j < NC; ++j)
#pragma unroll
                        for (int i = 0; i < NC; ++i)
                            if (i >= j) Lm[i][j] = sQ[NS + i][NS + j];
#pragma unroll
                    for (int j = 0; j < NC; ++j) {
                        float r = rsqrtf(Lm[j][j]);
                        invd[j] = r;
#pragma unroll
                        for (int i = j + 1; i < NC; ++i) Lm[i][j] *= r;
#pragma unroll
                        for (int i = j + 1; i < NC; ++i)
#pragma unroll
                            for (int l = j + 1; l <= i; ++l)
                                Lm[i][l] = fmaf(-Lm[i][j], Lm[l][j], Lm[i][l]);
                    }
                }
                // wait for warp1's Qux (it arrived long ago)
                asm volatile("bar.sync 1, 64;" ::: "memory");
                if (tid <= NS) {
                    float y[NC];
#pragma unroll
                    for (int a = 0; a < NC; ++a)
                        y[a] = (tid < NS) ? sQ[NS + a][tid] : sq[NS + a];
#pragma unroll
                    for (int a = 0; a < NC; ++a) {        // L z = y
                        float s = y[a];
#pragma unroll
                        for (int k = 0; k < a; ++k) s = fmaf(-Lm[a][k], y[k], s);
                        y[a] = s * invd[a];
                    }
#pragma unroll
                    for (int a = NC - 1; a >= 0; --a) {   // L^T w = z
                        float s = y[a];
#pragma unroll
                        for (int k = a + 1; k < NC; ++k) s = fmaf(-Lm[k][a], y[k], s);
                        y[a] = s * invd[a];
                    }
                    if (tid < NS) {
#pragma unroll
                        for (int a = 0; a < NC; ++a) sK[a][tid] = y[a];
                    } else {
#pragma unroll
                        for (int a = 0; a < NC; ++a) skk[a] = y[a];
                    }
                }
            } else {
                // warp 1: Qux quads
                float4 s = creg;
                if (notlast) {
#pragma unroll
                    for (int k = 0; k < NS; ++k) {
                        float f = Fc[k];
                        float4 w = *(const float4*)&sW[k][4 * rq];
                        s.x = fmaf(f, w.x, s.x); s.y = fmaf(f, w.y, s.y);
                        s.z = fmaf(f, w.z, s.z); s.w = fmaf(f, w.w, s.w);
                    }
                }
                *(float4*)&sQ[rrow][4 * rq] = s;
                if (t > 0) creg = C4[(t - 1) * CST4 + rrow * 6 + rq];
                asm volatile("bar.sync 1, 64;" ::: "memory");
            }
        } else {
            // warps 2-4: Qxx quads (+ qx for tid 64..79), in CD shadow
            float4 s = creg;
            if (notlast) {
#pragma unroll
                for (int k = 0; k < NS; ++k) {
                    float f = Fc[k];
                    float4 w = *(const float4*)&sW[k][4 * rq];
                    s.x = fmaf(f, w.x, s.x); s.y = fmaf(f, w.y, s.y);
                    s.z = fmaf(f, w.z, s.z); s.w = fmaf(f, w.w, s.w);
                }
            }
            *(float4*)&sQ[rrow][4 * rq] = s;
            if (t > 0) creg = C4[(t - 1) * CST4 + rrow * 6 + rq];
            if (tid < 80) {
                int i = tid - 64;
                float s2 = cq;
                if (notlast) {
#pragma unroll
                    for (int k = 0; k < NS; ++k) s2 = fmaf(sF[k][i], sp[k], s2);
                }
                sq[i] = s2;
                if (t > 0) cq = c[(t - 1) * NA + i];
            }
        }
        __syncthreads();

        // ---- Phase E: P, p, Acl, bias ----
        if (tid < 64) {                 // P = Qxx - Qxu K
            int i = tid & 15, jq = tid >> 4;
            float4 s = *(const float4*)&sQ[i][4 * jq];
            float4 q0 = *(const float4*)&sQ[i][NS];
            float4 q1 = *(const float4*)&sQ[i][NS + 4];
#pragma unroll
            for (int m = 0; m < NC; ++m) {
                float qm = (m == 0) ? q0.x : (m == 1) ? q0.y : (m == 2) ? q0.z : (m == 3) ? q0.w
                         : (m == 4) ? q1.x : (m == 5) ? q1.y : (m == 6) ? q1.z : q1.w;
                float4 kv = *(const float4*)&sK[m][4 * jq];
                s.x = fmaf(-qm, kv.x, s.x); s.y = fmaf(-qm, kv.y, s.y);
                s.z = fmaf(-qm, kv.z, s.z); s.w = fmaf(-qm, kv.w, s.w);
            }
            *(float4*)&sP[i][4 * jq] = s;
            *(float4*)&g_P[t][i][4 * jq] = s;
        } else if (tid < 80) {          // p = qx - Qxu kk
            int i = tid - 64;
            float4 q0 = *(const float4*)&sQ[i][NS];
            float4 q1 = *(const float4*)&sQ[i][NS + 4];
            float s = sq[i];
            s = fmaf(-q0.x, skk[0], s); s = fmaf(-q0.y, skk[1], s);
            s = fmaf(-q0.z, skk[2], s); s = fmaf(-q0.w, skk[3], s);
            s = fmaf(-q1.x, skk[4], s); s = fmaf(-q1.y, skk[5], s);
            s = fmaf(-q1.z, skk[6], s); s = fmaf(-q1.w, skk[7], s);
            sp[i] = s; g_p[t][i] = s;
        } else if (tid < 144) {         // Acl = A - B K
            int idx = tid - 80, i = idx & 15, jq = idx >> 4;
            float4 s = *(const float4*)&sF[i][4 * jq];
            float4 b0 = *(const float4*)&sF[i][NS];
            float4 b1 = *(const float4*)&sF[i][NS + 4];
#pragma unroll
            for (int m = 0; m < NC; ++m) {
                float bm = (m == 0) ? b0.x : (m == 1) ? b0.y : (m == 2) ? b0.z : (m == 3) ? b0.w
                         : (m == 4) ? b1.x : (m == 5) ? b1.y : (m == 6) ? b1.z : b1.w;
                float4 kv = *(const float4*)&sK[m][4 * jq];
                s.x = fmaf(-bm, kv.x, s.x); s.y = fmaf(-bm, kv.y, s.y);
                s.z = fmaf(-bm, kv.z, s.z); s.w = fmaf(-bm, kv.w, s.w);
            }
            float* ap = &sAcl[(t * NS + i) * AS + 4 * jq];
            ap[0] = s.x; ap[1] = s.y; ap[2] = s.z; ap[3] = s.w;
        } else {                        // bias = -B kk
            int i = tid - 144;
            float4 b0 = *(const float4*)&sF[i][NS];
            float4 b1 = *(const float4*)&sF[i][NS + 4];
            float s = 0.f;
            s = fmaf(-b0.x, skk[0], s); s = fmaf(-b0.y, skk[1], s);
            s = fmaf(-b0.z, skk[2], s); s = fmaf(-b0.w, skk[3], s);
            s = fmaf(-b1.x, skk[4], s); s = fmaf(-b1.y, skk[5], s);
            s = fmaf(-b1.z, skk[6], s); s = fmaf(-b1.w, skk[7], s);
            sBias[t][i] = s;
        }
        __syncthreads();
    }

    // ---- flush K_0 to global ----
    if (tid < 32) ((float4*)&g_K[0][0][0])[tid] = ((const float4*)&sK[0][0])[tid];
    else if (tid < 40) g_kk[0][tid - 32] = skk[tid - 32];

    // ---------------- Forward rollout: single warp, shuffle recurrence ----------------
    if (tid < 32) {
        int i = tid & 15;
        float x = (tid < NS) ? x0[tid] : 0.f;
#pragma unroll 1
        for (int t = 0; t < TT; ++t) {
            if (tid < NS) { out[t * NA + tid] = x; sX[t][tid] = x; }
            if (t < TT - 1) {
                float s = sBias[t][i];
                const float* ar = &sAcl[(t * NS + i) * AS];
#pragma unroll
                for (int k = 0; k < NS; ++k) {
                    float xk = __shfl_sync(0xffffffffu, x, k);
                    s = fmaf(ar[k], xk, s);
                }
                x = s;
            }
        }
    }
    __syncthreads();

    // ---------------- Parallel output post-pass ----------------
    for (int idx = tid; idx < TT * NC; idx += NTHR) {
        int t = idx >> 3, m = idx & 7;
        float s = g_kk[t][m];
        const float4* Kr = (const float4*)&g_K[t][m][0];
        const float* xr = &sX[t][0];
#pragma unroll
        for (int q = 0; q < 4; ++q) {
            float4 v = Kr[q];
            s = fmaf(v.x, xr[4 * q + 0], s); s = fmaf(v.y, xr[4 * q + 1], s);
            s = fmaf(v.z, xr[4 * q + 2], s); s = fmaf(v.w, xr[4 * q + 3], s);
        }
        out[t * NA + NS + m] = -s;
    }
    for (int idx = tid; idx < TT * NS; idx += NTHR) {
        int t = idx >> 4, i = idx & 15;
        float s = g_p[t][i];
        const float4* Pr = (const float4*)&g_P[t][i][0];
        const float* xr = &sX[t][0];
#pragma unroll
        for (int q = 0; q < 4; ++q) {
            float4 v = Pr[q];
            s = fmaf(v.x, xr[4 * q + 0], s); s = fmaf(v.y, xr[4 * q + 1], s);
            s = fmaf(v.z, xr[4 * q + 2], s); s = fmaf(v.w, xr[4 * q + 3], s);
        }
        out[TT * NA + idx] = (t == 0) ? -s : s;
    }
}

extern "C" void kernel_launch(void* const* d_in, const int* in_sizes, int n_in,
                              void* d_out, int out_size) {
    const float* A  = (const float*)d_in[0];
    const float* B  = (const float*)d_in[1];
    const float* x0 = (const float*)d_in[2];
    const float* C  = (const float*)d_in[3];
    const float* c  = (const float*)d_in[4];
    float* out = (float*)d_out;

    const int dyn = TT * NS * AS * sizeof(float);  // 139264 B
    cudaFuncSetAttribute(lqr_kernel, cudaFuncAttributeMaxDynamicSharedMemorySize, dyn);
    lqr_kernel<<<1, NTHR, dyn>>>(A, B, x0, C, c, out);
}

// round 9
// speedup vs baseline: 2.5204x; 2.5204x over previous
#include <cuda_runtime.h>

// LQR solved by PARALLEL-IN-TIME associative scan of Riccati value-function
// elements (A,b,C,J,eta), instead of a 128-step serial backward recursion.
// T=128, n_state=16, n_ctrl=8, n_all=24.

constexpr int TT = 128, NS = 16, NC = 8, NA = 24;

// Element buffers, double-buffered by scan parity.
__device__ float EA_[2][TT][NS * NS];
__device__ float EC_[2][TT][NS * NS];
__device__ float EJ_[2][TT][NS * NS];
__device__ float Eb_[2][TT][NS];
__device__ float Ee_[2][TT][NS];
// Per-stage gains for forward pass.
__device__ __align__(16) float gK_[TT][NC][NS];
__device__ float gkk_[TT][NC];
__device__ __align__(16) float gAcl_[TT][NS * NS];
__device__ __align__(16) float gbias_[TT][NS];

// ---------------------------------------------------------------------------
// Leaf: per stage t build element. Schur-eliminate u from the stage cost:
//  M = Cuu^{-1} Cux, m = Cuu^{-1} cu, Y = Cuu^{-1} B'
//  J = Cxx - Cxu M ; eta = Cxu m - cx ; At = A - B M ; b = -B m ; Cm = B Y
// Stage 127 is the terminal element: A=C=b=0 (J,eta only).
// ---------------------------------------------------------------------------
__global__ void __launch_bounds__(128, 1) leaf_kernel(
    const float* __restrict__ A, const float* __restrict__ B,
    const float* __restrict__ C, const float* __restrict__ c)
{
    const int t = blockIdx.x, tid = threadIdx.x;
    __shared__ float sC[NA][NA + 1];
    __shared__ float sc[NA];
    __shared__ float sA[NS][NS + 1];
    __shared__ float sB[NS][NC + 1];
    __shared__ float sM[NC][NS + 1];
    __shared__ float sY[NC][NS + 1];
    __shared__ float sm[NC];

    for (int idx = tid; idx < NA * NA; idx += 128) sC[idx / NA][idx % NA] = C[t * NA * NA + idx];
    for (int idx = tid; idx < NA; idx += 128)      sc[idx] = c[t * NA + idx];
    for (int idx = tid; idx < NS * NS; idx += 128) sA[idx / NS][idx % NS] = A[idx];
    for (int idx = tid; idx < NS * NC; idx += 128) sB[idx / NC][idx % NC] = B[idx];
    __syncthreads();

    if (tid < 33) {
        // redundant per-thread Cholesky of Cuu (scaled-column form)
        float Lm[NC][NC], invd[NC], y[NC];
#pragma unroll
        for (int j = 0; j < NC; ++j)
#pragma unroll
            for (int i = 0; i < NC; ++i)
                if (i >= j) Lm[i][j] = sC[NS + i][NS + j];
#pragma unroll
        for (int j = 0; j < NC; ++j) {
            float r = rsqrtf(Lm[j][j]);
            invd[j] = r;
#pragma unroll
            for (int i = j + 1; i < NC; ++i) Lm[i][j] *= r;
#pragma unroll
            for (int i = j + 1; i < NC; ++i)
#pragma unroll
                for (int l = j + 1; l <= i; ++l)
                    Lm[i][l] = fmaf(-Lm[i][j], Lm[l][j], Lm[i][l]);
        }
#pragma unroll
        for (int a = 0; a < NC; ++a)
            y[a] = (tid < 16) ? sC[NS + a][tid]
                 : (tid < 32) ? sB[tid - 16][a]
                              : sc[NS + a];
#pragma unroll
        for (int a = 0; a < NC; ++a) {
            float s = y[a];
#pragma unroll
            for (int k = 0; k < a; ++k) s = fmaf(-Lm[a][k], y[k], s);
            y[a] = s * invd[a];
        }
#pragma unroll
        for (int a = NC - 1; a >= 0; --a) {
            float s = y[a];
#pragma unroll
            for (int k = a + 1; k < NC; ++k) s = fmaf(-Lm[k][a], y[k], s);
            y[a] = s * invd[a];
        }
        if (tid < 16) {
#pragma unroll
            for (int a = 0; a < NC; ++a) sM[a][tid] = y[a];
        } else if (tid < 32) {
#pragma unroll
            for (int a = 0; a < NC; ++a) sY[a][tid - 16] = y[a];
        } else {
#pragma unroll
            for (int a = 0; a < NC; ++a) sm[a] = y[a];
        }
    }
    __syncthreads();

    const bool last = (t == TT - 1);
    for (int idx = tid; idx < NS * NS; idx += 128) {
        int i = idx >> 4, j = idx & 15;
        float vJ = sC[i][j], vA = sA[i][j], vC = 0.f;
#pragma unroll
        for (int a = 0; a < NC; ++a) {
            float cxu = sC[i][NS + a], bb = sB[i][a];
            vJ = fmaf(-cxu, sM[a][j], vJ);
            vA = fmaf(-bb, sM[a][j], vA);
            vC = fmaf(bb, sY[a][j], vC);
        }
        EJ_[0][t][idx] = vJ;
        EA_[0][t][idx] = last ? 0.f : vA;
        EC_[0][t][idx] = last ? 0.f : vC;
    }
    if (tid < NS) {
        float e = -sc[tid], b = 0.f;
#pragma unroll
        for (int a = 0; a < NC; ++a) {
            e = fmaf(sC[tid][NS + a], sm[a], e);
            b = fmaf(-sB[tid][a], sm[a], b);
        }
        Ee_[0][t][tid] = e;
        Eb_[0][t][tid] = last ? 0.f : b;
    }
}

// ---------------------------------------------------------------------------
// Combine (suffix Hillis-Steele level): out[t] = elem[t] (x) elem[t+d]
//   i = elem[t] (earlier), j = elem[t+d] (later)
//   S = I + Ci*Jj ; solve S*[XA|Xb|XC] = [Ai | bi+Ci*etaj | Ci] (GJ, warp 0)
//   Aout = Aj XA ; bout = Aj Xb + bj ; Cout = (Aj XC) Aj' + Cj
//   Jout = Ji + Ai' (Jj XA) ; etaout = etai + Ai' (etaj - Jj Xb)
// ---------------------------------------------------------------------------
__global__ void __launch_bounds__(128, 1) combine_kernel(int d, int src)
{
    const int t = blockIdx.x, tid = threadIdx.x;
    const int dst = src ^ 1;
    if (t + d > TT - 1) {
        for (int idx = tid; idx < NS * NS; idx += 128) {
            EA_[dst][t][idx] = EA_[src][t][idx];
            EC_[dst][t][idx] = EC_[src][t][idx];
            EJ_[dst][t][idx] = EJ_[src][t][idx];
        }
        if (tid < NS) {
            Eb_[dst][t][tid] = Eb_[src][t][tid];
            Ee_[dst][t][tid] = Ee_[src][t][tid];
        }
        return;
    }
    const int tj = t + d;
    __shared__ float sAi[NS][NS + 1], sCi[NS][NS + 1];
    __shared__ float sAj[NS][NS + 1], sJj[NS][NS + 1];
    __shared__ float sS[NS][NS + 1];
    __shared__ float sXAT[NS][NS + 1], sXCT[NS][NS + 1];
    __shared__ float sG[NS][NS + 1], sH[NS][NS + 1];
    __shared__ float sbi[NS], setai[NS], sbj[NS], setaj[NS];
    __shared__ float sv[NS], sw[NS], sXb[NS];

    for (int idx = tid; idx < NS * NS; idx += 128) {
        int r = idx >> 4, cc = idx & 15;
        sAi[r][cc] = EA_[src][t][idx];
        sCi[r][cc] = EC_[src][t][idx];
        sAj[r][cc] = EA_[src][tj][idx];
        sJj[r][cc] = EJ_[src][tj][idx];
    }
    if (tid < NS) {
        sbi[tid] = Eb_[src][t][tid];   setai[tid] = Ee_[src][t][tid];
        sbj[tid] = Eb_[src][tj][tid];  setaj[tid] = Ee_[src][tj][tid];
    }
    __syncthreads();

    // S = I + Ci*Jj ; v = bi + Ci*etaj
    for (int idx = tid; idx < NS * NS; idx += 128) {
        int r = idx >> 4, cc = idx & 15;
        float s = (r == cc) ? 1.f : 0.f;
#pragma unroll
        for (int k = 0; k < NS; ++k) s = fmaf(sCi[r][k], sJj[k][cc], s);
        sS[r][cc] = s;
    }
    if (tid < NS) {
        float s = sbi[tid];
#pragma unroll
        for (int k = 0; k < NS; ++k) s = fmaf(sCi[tid][k], setaj[k], s);
        sv[tid] = s;
    }
    __syncthreads();

    // GJ solve by warp 0: columns in registers, pivot column via shuffles.
    if (tid < 32) {
        const int c1 = tid;        // cols 0..31: 0..15 = S, 16..31 = RHS(Ai)
        const int c2 = tid + 32;   // cols 32..48: 32 = v, 33..48 = RHS(Ci)
        float colA[NS], colB[NS];
#pragma unroll
        for (int r = 0; r < NS; ++r) {
            colA[r] = (c1 < NS) ? sS[r][c1] : sAi[r][c1 - NS];
            colB[r] = (tid == 0) ? sv[r] : ((tid <= 16) ? sCi[r][tid - 1] : 0.f);
        }
#pragma unroll
        for (int p = 0; p < NS; ++p) {
            float f[NS];
#pragma unroll
            for (int r = 0; r < NS; ++r) f[r] = __shfl_sync(0xffffffffu, colA[r], p);
            float inv = __fdividef(1.f, f[p]);
            float mA = colA[p] * inv, mB = colB[p] * inv;
            colA[p] = mA; colB[p] = mB;
#pragma unroll
            for (int r = 0; r < NS; ++r) {
                if (r != p) {
                    colA[r] = fmaf(-f[r], mA, colA[r]);
                    colB[r] = fmaf(-f[r], mB, colB[r]);
                }
            }
        }
        if (c1 >= NS) {
#pragma unroll
            for (int r = 0; r < NS; ++r) sXAT[c1 - NS][r] = colA[r];  // XA^T
        }
        if (tid == 0) {
#pragma unroll
            for (int r = 0; r < NS; ++r) sXb[r] = colB[r];
        } else if (tid <= 16) {
#pragma unroll
            for (int r = 0; r < NS; ++r) sXCT[tid - 1][r] = colB[r];  // XC^T
        }
    }
    __syncthreads();

    // Round 1: Aout, G = Aj*XC, H = Jj*XA, bout, w
    for (int idx = tid; idx < NS * NS; idx += 128) {
        int r = idx >> 4, cc = idx & 15;
        float a = 0.f, g = 0.f, h = 0.f;
#pragma unroll
        for (int k = 0; k < NS; ++k) {
            a = fmaf(sAj[r][k], sXAT[cc][k], a);
            g = fmaf(sAj[r][k], sXCT[cc][k], g);
            h = fmaf(sJj[r][k], sXAT[cc][k], h);
        }
        EA_[dst][t][idx] = a;
        sG[r][cc] = g;
        sH[r][cc] = h;
    }
    if (tid < NS) {
        float b = sbj[tid], w = setaj[tid];
#pragma unroll
        for (int k = 0; k < NS; ++k) {
            b = fmaf(sAj[tid][k], sXb[k], b);
            w = fmaf(-sJj[tid][k], sXb[k], w);
        }
        Eb_[dst][t][tid] = b;
        sw[tid] = w;
    }
    __syncthreads();

    // Round 2: Cout = G*Aj' + Cj ; Jout = Ai'*H + Ji ; etaout = etai + Ai'*w
    for (int idx = tid; idx < NS * NS; idx += 128) {
        int r = idx >> 4, cc = idx & 15;
        float cv = EC_[src][tj][idx];
        float jv = EJ_[src][t][idx];
#pragma unroll
        for (int k = 0; k < NS; ++k) {
            cv = fmaf(sG[r][k], sAj[cc][k], cv);
            jv = fmaf(sAi[k][r], sH[k][cc], jv);
        }
        EC_[dst][t][idx] = cv;
        EJ_[dst][t][idx] = jv;
    }
    if (tid < NS) {
        float e = setai[tid];
#pragma unroll
        for (int k = 0; k < NS; ++k) e = fmaf(sAi[k][tid], sw[k], e);
        Ee_[dst][t][tid] = e;
    }
}

// ---------------------------------------------------------------------------
// Gains: per stage t (parallel): Quu = Cuu + B'P'B, Qux = Cux + B'P'A,
// qu = cu + B'p'  (P' = P_{t+1} = EJ[1][t+1], zero at t=127); K, kk, Acl, bias.
// ---------------------------------------------------------------------------
__global__ void __launch_bounds__(128, 1) gains_kernel(
    const float* __restrict__ A, const float* __restrict__ B,
    const float* __restrict__ C, const float* __restrict__ c)
{
    const int t = blockIdx.x, tid = threadIdx.x;
    __shared__ float sP[NS][NS + 1], sp[NS];
    __shared__ float sA[NS][NS + 1], sB[NS][NC + 1];
    __shared__ float sG[NS][NS + 1], sGb[NS][NC + 1];
    __shared__ float sQuu[NC][NC + 1], sQux[NC][NS + 1], squ[NC];
    __shared__ float sK[NC][NS + 1], skk[NC];
    __shared__ float sCu[NC][NA + 1], scu[NC];

    const bool haveP = (t < TT - 1);
    for (int idx = tid; idx < NS * NS; idx += 128) {
        sP[idx >> 4][idx & 15] = haveP ? EJ_[1][t + 1][idx] : 0.f;
        sA[idx >> 4][idx & 15] = A[idx];
    }
    for (int idx = tid; idx < NS * NC; idx += 128) sB[idx / NC][idx % NC] = B[idx];
    if (tid < NS) sp[tid] = haveP ? -Ee_[1][t + 1][tid] : 0.f;
    for (int idx = tid; idx < NC * NA; idx += 128)
        sCu[idx / NA][idx % NA] = C[t * NA * NA + (NS + idx / NA) * NA + (idx % NA)];
    if (tid < NC) scu[tid] = c[t * NA + NS + tid];
    __syncthreads();

    // G = P'A, Gb = P'B
    for (int idx = tid; idx < NS * NS; idx += 128) {
        int i = idx >> 4, j = idx & 15;
        float s = 0.f;
#pragma unroll
        for (int k = 0; k < NS; ++k) s = fmaf(sP[i][k], sA[k][j], s);
        sG[i][j] = s;
    }
    for (int idx = tid; idx < NS * NC; idx += 128) {
        int i = idx / NC, j = idx % NC;
        float s = 0.f;
#pragma unroll
        for (int k = 0; k < NS; ++k) s = fmaf(sP[i][k], sB[k][j], s);
        sGb[i][j] = s;
    }
    __syncthreads();

    // Quu, Qux, qu
    for (int idx = tid; idx < NC * NC; idx += 128) {
        int a = idx >> 3, b2 = idx & 7;
        float s = sCu[a][NS + b2];
#pragma unroll
        for (int i = 0; i < NS; ++i) s = fmaf(sB[i][a], sGb[i][b2], s);
        sQuu[a][b2] = s;
    }
    for (int idx = tid; idx < NC * NS; idx += 128) {
        int a = idx >> 4, j = idx & 15;
        float s = sCu[a][j];
#pragma unroll
        for (int i = 0; i < NS; ++i) s = fmaf(sB[i][a], sG[i][j], s);
        sQux[a][j] = s;
    }
    if (tid < NC) {
        float s = scu[tid];
#pragma unroll
        for (int i = 0; i < NS; ++i) s = fmaf(sB[i][tid], sp[i], s);
        squ[tid] = s;
    }
    __syncthreads();

    if (tid < 17) {
        float Lm[NC][NC], invd[NC], y[NC];
#pragma unroll
        for (int j = 0; j < NC; ++j)
#pragma unroll
            for (int i = 0; i < NC; ++i)
                if (i >= j) Lm[i][j] = sQuu[i][j];
#pragma unroll
        for (int j = 0; j < NC; ++j) {
            float r = rsqrtf(Lm[j][j]);
            invd[j] = r;
#pragma unroll
            for (int i = j + 1; i < NC; ++i) Lm[i][j] *= r;
#pragma unroll
            for (int i = j + 1; i < NC; ++i)
#pragma unroll
                for (int l = j + 1; l <= i; ++l)
                    Lm[i][l] = fmaf(-Lm[i][j], Lm[l][j], Lm[i][l]);
        }
#pragma unroll
        for (int a = 0; a < NC; ++a)
            y[a] = (tid < NS) ? sQux[a][tid] : squ[a];
#pragma unroll
        for (int a = 0; a < NC; ++a) {
            float s = y[a];
#pragma unroll
            for (int k = 0; k < a; ++k) s = fmaf(-Lm[a][k], y[k], s);
            y[a] = s * invd[a];
        }
#pragma unroll
        for (int a = NC - 1; a >= 0; --a) {
            float s = y[a];
#pragma unroll
            for (int k = a + 1; k < NC; ++k) s = fmaf(-Lm[k][a], y[k], s);
            y[a] = s * invd[a];
        }
        if (tid < NS) {
#pragma unroll
            for (int a = 0; a < NC; ++a) { sK[a][tid] = y[a]; gK_[t][a][tid] = y[a]; }
        } else {
#pragma unroll
            for (int a = 0; a < NC; ++a) { skk[a] = y[a]; gkk_[t][a] = y[a]; }
        }
    }
    __syncthreads();

    for (int idx = tid; idx < NS * NS; idx += 128) {
        int i = idx >> 4, j = idx & 15;
        float s = sA[i][j];
#pragma unroll
        for (int a = 0; a < NC; ++a) s = fmaf(-sB[i][a], sK[a][j], s);
        gAcl_[t][idx] = s;
    }
    if (tid < NS) {
        float s = 0.f;
#pragma unroll
        for (int a = 0; a < NC; ++a) s = fmaf(-sB[tid][a], skk[a], s);
        gbias_[t][tid] = s;
    }
}

// ---------------------------------------------------------------------------
// Final: preload Acl/bias to shared, single-warp shuffle rollout, then
// parallel outputs: z (x,u) and mu_t = P_t x_t + p_t (negated at t=0).
// ---------------------------------------------------------------------------
__global__ void __launch_bounds__(256, 1) final_kernel(
    const float* __restrict__ x0, float* __restrict__ out)
{
    extern __shared__ float sAcl[];       // [TT][NS][17]
    __shared__ float sBias[TT][NS];
    __shared__ float sX[TT][NS];
    const int tid = threadIdx.x;

    const float4* g4 = (const float4*)gAcl_;
    for (int q = tid; q < TT * NS * 4; q += 256) {
        float4 v = g4[q];
        int t = q >> 6, rem = q & 63;
        int i = rem >> 2, j0 = (rem & 3) * 4;
        float* dp = &sAcl[(t * NS + i) * 17 + j0];
        dp[0] = v.x; dp[1] = v.y; dp[2] = v.z; dp[3] = v.w;
    }
    {
        const float4* b4 = (const float4*)gbias_;
        float4* s4 = (float4*)&sBias[0][0];
        for (int q = tid; q < TT * NS / 4; q += 256) s4[q] = b4[q];
    }
    __syncthreads();

    if (tid < 32) {
        int i = tid & 15;
        float x = (tid < NS) ? x0[tid] : 0.f;
#pragma unroll 1
        for (int t = 0; t < TT; ++t) {
            if (tid < NS) { out[t * NA + tid] = x; sX[t][tid] = x; }
            if (t < TT - 1) {
                float s = sBias[t][i];
                const float* ar = &sAcl[(t * NS + i) * 17];
#pragma unroll
                for (int k = 0; k < NS; ++k) {
                    float xk = __shfl_sync(0xffffffffu, x, k);
                    s = fmaf(ar[k], xk, s);
                }
                x = s;
            }
        }
    }
    __syncthreads();

    // u_t = -(K_t x_t + kk_t)
    for (int idx = tid; idx < TT * NC; idx += 256) {
        int t = idx >> 3, m = idx & 7;
        float s = gkk_[t][m];
        const float4* Kr = (const float4*)&gK_[t][m][0];
        const float* xr = &sX[t][0];
#pragma unroll
        for (int q = 0; q < 4; ++q) {
            float4 v = Kr[q];
            s = fmaf(v.x, xr[4 * q + 0], s); s = fmaf(v.y, xr[4 * q + 1], s);
            s = fmaf(v.z, xr[4 * q + 2], s); s = fmaf(v.w, xr[4 * q + 3], s);
        }
        out[t * NA + NS + m] = -s;
    }
    // mu_t = P_t x_t + p_t = EJ[1][t] x_t - Ee[1][t]
    for (int idx = tid; idx < TT * NS; idx += 256) {
        int t = idx >> 4, i = idx & 15;
        float s = -Ee_[1][t][i];
        const float4* Pr = (const float4*)&EJ_[1][t][i * NS];
        const float* xr = &sX[t][0];
#pragma unroll
        for (int q = 0; q < 4; ++q) {
            float4 v = Pr[q];
            s = fmaf(v.x, xr[4 * q + 0], s); s = fmaf(v.y, xr[4 * q + 1], s);
            s = fmaf(v.z, xr[4 * q + 2], s); s = fmaf(v.w, xr[4 * q + 3], s);
        }
        out[TT * NA + idx] = (t == 0) ? -s : s;
    }
}

extern "C" void kernel_launch(void* const* d_in, const int* in_sizes, int n_in,
                              void* d_out, int out_size) {
    const float* A  = (const float*)d_in[0];
    const float* B  = (const float*)d_in[1];
    const float* x0 = (const float*)d_in[2];
    const float* C  = (const float*)d_in[3];
    const float* c  = (const float*)d_in[4];
    float* out = (float*)d_out;

    leaf_kernel<<<TT, 128>>>(A, B, C, c);
    for (int k = 0; k < 7; ++k)
        combine_kernel<<<TT, 128>>>(1 << k, k & 1);
    gains_kernel<<<TT, 128>>>(A, B, C, c);

    const int dyn = TT * NS * 17 * sizeof(float);  // 139264 B
    cudaFuncSetAttribute(final_kernel, cudaFuncAttributeMaxDynamicSharedMemorySize, dyn);
    final_kernel<<<1, 256, dyn>>>(x0, out);
}